// round 4
// baseline (speedup 1.0000x reference)
#include <cuda_runtime.h>
#include <cuda_bf16.h>
#include <stdint.h>

typedef __nv_bfloat16 bf16;
#define NB 2
#define NL 2048
#define ND 1024
#define NH 16

// ---------------- scratch ----------------
__device__ bf16 g_iqh[NB*NL*ND], g_iql[NB*NL*ND];
__device__ bf16 g_ikh[NB*NL*ND], g_ikl[NB*NL*ND];
__device__ bf16 g_ivh[NB*NL*ND], g_ivl[NB*NL*ND];
__device__ bf16 g_wqh[ND*ND], g_wql[ND*ND];
__device__ bf16 g_wkh[ND*ND], g_wkl[ND*ND];
__device__ bf16 g_wvh[ND*ND], g_wvl[ND*ND];
__device__ bf16 g_woh[ND*ND], g_wol[ND*ND];
__device__ bf16 g_qh[NB*NH*NL*64], g_ql[NB*NH*NL*64];
__device__ bf16 g_kh[NB*NH*NL*64], g_kl[NB*NH*NL*64];
__device__ bf16 g_vh[NB*NH*NL*64], g_vl[NB*NH*NL*64];
__device__ bf16 g_ch[(size_t)NB*NL*ND], g_cl[(size_t)NB*NL*ND];

// ---------------- helpers ----------------
__device__ __forceinline__ uint32_t s2u(const void* p){ return (uint32_t)__cvta_generic_to_shared(p); }
__device__ __forceinline__ void cpa16(uint32_t d, const void* s){
    asm volatile("cp.async.cg.shared.global [%0],[%1],16;"::"r"(d),"l"(s));
}
__device__ __forceinline__ void cp_commit(){ asm volatile("cp.async.commit_group;"); }
__device__ __forceinline__ void cp_wait0(){ asm volatile("cp.async.wait_group 0;"); }
__device__ __forceinline__ void cp_wait1(){ asm volatile("cp.async.wait_group 1;"); }

__device__ __forceinline__ void ldsm4(uint32_t* r, uint32_t a){
    asm volatile("ldmatrix.sync.aligned.m8n8.x4.shared.b16 {%0,%1,%2,%3},[%4];"
                 : "=r"(r[0]),"=r"(r[1]),"=r"(r[2]),"=r"(r[3]) : "r"(a));
}
__device__ __forceinline__ void ldsm4t(uint32_t* r, uint32_t a){
    asm volatile("ldmatrix.sync.aligned.m8n8.x4.trans.shared.b16 {%0,%1,%2,%3},[%4];"
                 : "=r"(r[0]),"=r"(r[1]),"=r"(r[2]),"=r"(r[3]) : "r"(a));
}
__device__ __forceinline__ void mma_bf16(float* c, const uint32_t* a, const uint32_t* b){
    asm volatile("mma.sync.aligned.m16n8k16.row.col.f32.bf16.bf16.f32 "
                 "{%0,%1,%2,%3},{%4,%5,%6,%7},{%8,%9},{%0,%1,%2,%3};"
                 : "+f"(c[0]),"+f"(c[1]),"+f"(c[2]),"+f"(c[3])
                 : "r"(a[0]),"r"(a[1]),"r"(a[2]),"r"(a[3]),"r"(b[0]),"r"(b[1]));
}
__device__ __forceinline__ uint32_t addrA(const bf16* base,int r0,int c0,int ln){
    int r=r0+(ln&7)+((ln&8)?8:0); int c=c0+((ln&16)?8:0); return s2u(base+r*72+c);
}
__device__ __forceinline__ uint32_t addrB(const bf16* base,int n0,int k0,int ln){
    int r=n0+(ln&7)+((ln&16)?8:0); int c=k0+((ln&8)?8:0); return s2u(base+r*72+c);
}
__device__ __forceinline__ void split_pack(float e,float o,uint32_t& hi,uint32_t& lo){
    bf16 he=__float2bfloat16(e), ho=__float2bfloat16(o);
    bf16 le=__float2bfloat16(e-__bfloat162float(he));
    bf16 lq=__float2bfloat16(o-__bfloat162float(ho));
    __nv_bfloat162 H; H.x=he; H.y=ho; __nv_bfloat162 L2; L2.x=le; L2.y=lq;
    hi=reinterpret_cast<uint32_t&>(H); lo=reinterpret_cast<uint32_t&>(L2);
}

// ---------------- batched split fp32 -> hi/lo bf16 (float4) ----------------
struct SplitArgs { const float* x[4]; bf16* h[4]; bf16* l[4]; };
__global__ __launch_bounds__(256) void splitN(SplitArgs sa, int n4){
    int z=blockIdx.y;
    const float* x=sa.x[z]; bf16* h=sa.h[z]; bf16* l=sa.l[z];
    int i=blockIdx.x*256+threadIdx.x;
    if(i<n4){
        float4 v=((const float4*)x)[i];
        uint32_t h0,l0,h1,l1;
        split_pack(v.x,v.y,h0,l0); split_pack(v.z,v.w,h1,l1);
        uint2 hh=make_uint2(h0,h1), ll=make_uint2(l0,l1);
        ((uint2*)h)[i]=hh; ((uint2*)l)[i]=ll;
    }
}

// ---------------- GEMM: C[4096,1024] = X @ W^T, split-bf16 x3, 3-stage cp.async ----------------
struct GArgs {
    const bf16 *xh[3], *xl[3], *wh[3], *wl[3];
    bf16 *oh[3], *ol[3];
    float *of[3];
};
__global__ __launch_bounds__(256) void gemm_bf(GArgs ga)
{
    extern __shared__ bf16 dyn[];
    const int z=blockIdx.z;
    const bf16* __restrict__ Xh=ga.xh[z]; const bf16* __restrict__ Xl=ga.xl[z];
    const bf16* __restrict__ Wh=ga.wh[z]; const bf16* __restrict__ Wl=ga.wl[z];
    bf16* Oh=ga.oh[z]; bf16* Ol=ga.ol[z]; float* Of=ga.of[z];

    const int tid=threadIdx.x, warp=tid>>5, lane=tid&31;
    const int wm=warp>>2, wn=warp&3;
    const int m0=blockIdx.y*128, n0=blockIdx.x*128;

    float acc[4][4][4];
    #pragma unroll
    for(int a=0;a<4;a++) for(int b=0;b<4;b++) for(int c=0;c<4;c++) acc[a][b][c]=0.f;

    const bf16* srcs[4]={Xh,Xl,Wh,Wl};
    const int rows0[4]={m0,m0,n0,n0};

    auto issue=[&](int chunk){
        int st=chunk%3, k0=chunk*64;
        #pragma unroll
        for(int t=0;t<4;t++){
            uint32_t base=s2u(dyn+(st*4+t)*9216);
            const bf16* src=srcs[t]; int r0=rows0[t];
            #pragma unroll
            for(int j=0;j<4;j++){
                int c=tid+256*j; int r=c>>3, q=c&7;
                cpa16(base+r*144+q*16, src+(size_t)(r0+r)*1024+k0+q*8);
            }
        }
        cp_commit();
    };

    issue(0); issue(1);
    for(int it=0; it<16; it++){
        if(it<15) cp_wait1(); else cp_wait0();
        __syncthreads();
        if(it+2<16) issue(it+2);
        const int st=it%3;
        const bf16* sAh=dyn+(st*4+0)*9216;
        const bf16* sAl=dyn+(st*4+1)*9216;
        const bf16* sBh=dyn+(st*4+2)*9216;
        const bf16* sBl=dyn+(st*4+3)*9216;
        #pragma unroll
        for(int kk=0;kk<64;kk+=16){
            uint32_t ah[4][4], al[4][4];
            #pragma unroll
            for(int mt=0;mt<4;mt++){
                ldsm4(ah[mt],addrA(sAh,wm*64+mt*16,kk,lane));
                ldsm4(al[mt],addrA(sAl,wm*64+mt*16,kk,lane));
            }
            #pragma unroll
            for(int p=0;p<2;p++){
                uint32_t bh[4],bl[4];
                ldsm4(bh,addrB(sBh,wn*32+p*16,kk,lane));
                ldsm4(bl,addrB(sBl,wn*32+p*16,kk,lane));
                #pragma unroll
                for(int mt=0;mt<4;mt++){
                    mma_bf16(acc[mt][2*p],ah[mt],bh+0);
                    mma_bf16(acc[mt][2*p],ah[mt],bl+0);
                    mma_bf16(acc[mt][2*p],al[mt],bh+0);
                    mma_bf16(acc[mt][2*p+1],ah[mt],bh+2);
                    mma_bf16(acc[mt][2*p+1],ah[mt],bl+2);
                    mma_bf16(acc[mt][2*p+1],al[mt],bh+2);
                }
            }
        }
    }

    const int g=lane>>2, tg=lane&3;
    #pragma unroll
    for(int mt=0;mt<4;mt++){
        #pragma unroll
        for(int nt=0;nt<4;nt++){
            int gm=m0+wm*64+mt*16+g, gn=n0+wn*32+nt*8+2*tg;
            float* a=acc[mt][nt];
            if(Of){
                *(float2*)(Of+(size_t)gm*1024+gn)=make_float2(a[0],a[1]);
                *(float2*)(Of+(size_t)(gm+8)*1024+gn)=make_float2(a[2],a[3]);
            }else{
                int h=gn>>6, d=gn&63;
                int b1=gm>>11, l1=gm&2047;
                size_t o1=((size_t)(b1*16+h)*2048+l1)*64+d;
                uint32_t hi,lo; split_pack(a[0],a[1],hi,lo);
                *(uint32_t*)(Oh+o1)=hi; *(uint32_t*)(Ol+o1)=lo;
                int gm2=gm+8; int b2=gm2>>11, l2=gm2&2047;
                size_t o2=((size_t)(b2*16+h)*2048+l2)*64+d;
                split_pack(a[2],a[3],hi,lo);
                *(uint32_t*)(Oh+o2)=hi; *(uint32_t*)(Ol+o2)=lo;
            }
        }
    }
}

// ---------------- attention ----------------
__device__ __forceinline__ void compute_scores(
    float s[16][4], const bf16* sqh,const bf16* sql,
    const bf16* skh,const bf16* skl,int wr0,int lane)
{
    #pragma unroll
    for(int nt=0;nt<16;nt++) for(int j=0;j<4;j++) s[nt][j]=0.f;
    #pragma unroll
    for(int kk=0;kk<64;kk+=16){
        uint32_t qah[4],qal[4];
        ldsm4(qah,addrA(sqh,wr0,kk,lane));
        ldsm4(qal,addrA(sql,wr0,kk,lane));
        #pragma unroll
        for(int p=0;p<8;p++){
            uint32_t kbh[4],kbl[4];
            ldsm4(kbh,addrB(skh,p*16,kk,lane));
            ldsm4(kbl,addrB(skl,p*16,kk,lane));
            mma_bf16(s[2*p],qah,kbh+0);
            mma_bf16(s[2*p],qah,kbl+0);
            mma_bf16(s[2*p],qal,kbh+0);
            mma_bf16(s[2*p+1],qah,kbh+2);
            mma_bf16(s[2*p+1],qah,kbl+2);
            mma_bf16(s[2*p+1],qal,kbh+2);
        }
    }
}
__device__ __forceinline__ void compute_scores_hi(
    float s[16][4], const bf16* sqh,const bf16* skh,int wr0,int lane)
{
    #pragma unroll
    for(int nt=0;nt<16;nt++) for(int j=0;j<4;j++) s[nt][j]=0.f;
    #pragma unroll
    for(int kk=0;kk<64;kk+=16){
        uint32_t qah[4];
        ldsm4(qah,addrA(sqh,wr0,kk,lane));
        #pragma unroll
        for(int p=0;p<8;p++){
            uint32_t kbh[4];
            ldsm4(kbh,addrB(skh,p*16,kk,lane));
            mma_bf16(s[2*p],qah,kbh+0);
            mma_bf16(s[2*p+1],qah,kbh+2);
        }
    }
}

__global__ __launch_bounds__(256) void attn_kernel(
    const bf16* __restrict__ qh,const bf16* __restrict__ ql,
    const bf16* __restrict__ kh,const bf16* __restrict__ kl,
    const bf16* __restrict__ vh,const bf16* __restrict__ vl,
    float* __restrict__ attn, bf16* __restrict__ ch, bf16* __restrict__ cl)
{
    extern __shared__ bf16 dyn[];
    bf16* sqh=dyn; bf16* sql=dyn+9216;
    const int tid=threadIdx.x, warp=tid>>5, lane=tid&31;
    const int g=lane>>2, tg=lane&3;
    const int bh=blockIdx.y, qb=blockIdx.x, wr0=warp*16;
    const size_t qoff=((size_t)bh*2048+qb*128)*64;

    auto loadT=[&](bf16* dst, const bf16* src, size_t off){
        uint32_t base=s2u(dst);
        #pragma unroll
        for(int j=0;j<4;j++){
            int c=tid+256*j; int r=c>>3, q=c&7;
            cpa16(base+r*144+q*16, src+off+(size_t)r*64+q*8);
        }
    };
    auto loadK1=[&](int st,int kt){      // hi only (pass 1)
        size_t koff=((size_t)bh*2048+kt*128)*64;
        loadT(dyn+(2+st*2+0)*9216, kh, koff);
    };
    auto loadKV=[&](int st,int kt){      // K hi/lo + V hi/lo (pass 2)
        size_t koff=((size_t)bh*2048+kt*128)*64;
        loadT(dyn+(2+st*2+0)*9216, kh, koff);
        loadT(dyn+(2+st*2+1)*9216, kl, koff);
        loadT(dyn+(6+st*2+0)*9216, vh, koff);
        loadT(dyn+(6+st*2+1)*9216, vl, koff);
    };

    float s[16][4];
    float lrun[2]={0.f,0.f};

    // ---- pass 1: row sums of exp (hi-only scores; |s|<~3 so no max needed) ----
    loadT(sqh,qh,qoff); loadT(sql,ql,qoff);
    loadK1(0,0); cp_commit();
    for(int kt=0;kt<16;kt++){
        cp_wait0();
        __syncthreads();
        if(kt<15){ loadK1((kt+1)&1,kt+1); cp_commit(); }
        compute_scores_hi(s,sqh,dyn+(2+(kt&1)*2)*9216,wr0,lane);
        #pragma unroll
        for(int nt=0;nt<16;nt++){
            lrun[0]+=__expf(s[nt][0]*0.125f)+__expf(s[nt][1]*0.125f);
            lrun[1]+=__expf(s[nt][2]*0.125f)+__expf(s[nt][3]*0.125f);
        }
    }
    #pragma unroll
    for(int rh=0;rh<2;rh++){
        lrun[rh]+=__shfl_xor_sync(0xffffffffu,lrun[rh],1);
        lrun[rh]+=__shfl_xor_sync(0xffffffffu,lrun[rh],2);
    }
    float inv[2]={1.f/lrun[0],1.f/lrun[1]};

    float o[8][4];
    #pragma unroll
    for(int a=0;a<8;a++) for(int b=0;b<4;b++) o[a][b]=0.f;

    // ---- pass 2: normalized attn write + P@V ----
    loadKV(0,0); cp_commit();
    for(int kt=0;kt<16;kt++){
        cp_wait0();
        __syncthreads();
        if(kt<15){ loadKV((kt+1)&1,kt+1); cp_commit(); }
        const bf16* skh=dyn+(2+(kt&1)*2+0)*9216;
        const bf16* skl=dyn+(2+(kt&1)*2+1)*9216;
        const bf16* svh=dyn+(6+(kt&1)*2+0)*9216;
        const bf16* svl=dyn+(6+(kt&1)*2+1)*9216;
        compute_scores(s,sqh,sql,skh,skl,wr0,lane);
        const int qrow0=qb*128+wr0+g;
        #pragma unroll
        for(int nt=0;nt<16;nt++){
            #pragma unroll
            for(int rh=0;rh<2;rh++){
                float p0=__expf(s[nt][2*rh]*0.125f)*inv[rh];
                float p1=__expf(s[nt][2*rh+1]*0.125f)*inv[rh];
                s[nt][2*rh]=p0; s[nt][2*rh+1]=p1;
                size_t ao=((size_t)bh*2048+(qrow0+8*rh))*2048+(size_t)kt*128+nt*8+2*tg;
                __stcs(reinterpret_cast<float2*>(attn+ao),make_float2(p0,p1));
            }
        }
        #pragma unroll
        for(int ks=0;ks<8;ks++){
            uint32_t a_h[4],a_l[4];
            split_pack(s[2*ks][0],s[2*ks][1],a_h[0],a_l[0]);
            split_pack(s[2*ks][2],s[2*ks][3],a_h[1],a_l[1]);
            split_pack(s[2*ks+1][0],s[2*ks+1][1],a_h[2],a_l[2]);
            split_pack(s[2*ks+1][2],s[2*ks+1][3],a_h[3],a_l[3]);
            #pragma unroll
            for(int p2=0;p2<4;p2++){
                uint32_t vbh[4],vbl[4];
                ldsm4t(vbh,addrA(svh,ks*16,p2*16,lane));
                ldsm4t(vbl,addrA(svl,ks*16,p2*16,lane));
                mma_bf16(o[2*p2],a_h,vbh+0);
                mma_bf16(o[2*p2],a_h,vbl+0);
                mma_bf16(o[2*p2],a_l,vbh+0);
                mma_bf16(o[2*p2+1],a_h,vbh+2);
                mma_bf16(o[2*p2+1],a_h,vbl+2);
                mma_bf16(o[2*p2+1],a_l,vbh+2);
            }
        }
    }

    const int b=bh>>4, h=bh&15;
    #pragma unroll
    for(int nt=0;nt<8;nt++){
        #pragma unroll
        for(int rh=0;rh<2;rh++){
            int row=qb*128+wr0+g+8*rh, d=nt*8+2*tg;
            size_t co=((size_t)b*2048+row)*1024+h*64+d;
            uint32_t hi,lo; split_pack(o[nt][2*rh],o[nt][2*rh+1],hi,lo);
            *(uint32_t*)(ch+co)=hi; *(uint32_t*)(cl+co)=lo;
        }
    }
}

extern "C" void kernel_launch(void* const* d_in, const int* in_sizes, int n_in,
                              void* d_out, int out_size) {
    const float* key  =(const float*)d_in[0];
    const float* value=(const float*)d_in[1];
    const float* query=(const float*)d_in[2];
    const float* wq=(const float*)d_in[3];
    const float* wk=(const float*)d_in[4];
    const float* wv=(const float*)d_in[5];
    const float* wo=(const float*)d_in[6];

    float* out=(float*)d_out;
    float* attn=out+(size_t)NB*NL*ND;

    bf16 *iqh,*iql,*ikh,*ikl,*ivh,*ivl;
    bf16 *wqh,*wql,*wkh,*wkl,*wvh,*wvl,*woh,*wol;
    bf16 *qh,*ql,*kh,*kl,*vh,*vl,*ch,*cl;
    cudaGetSymbolAddress((void**)&iqh,g_iqh); cudaGetSymbolAddress((void**)&iql,g_iql);
    cudaGetSymbolAddress((void**)&ikh,g_ikh); cudaGetSymbolAddress((void**)&ikl,g_ikl);
    cudaGetSymbolAddress((void**)&ivh,g_ivh); cudaGetSymbolAddress((void**)&ivl,g_ivl);
    cudaGetSymbolAddress((void**)&wqh,g_wqh); cudaGetSymbolAddress((void**)&wql,g_wql);
    cudaGetSymbolAddress((void**)&wkh,g_wkh); cudaGetSymbolAddress((void**)&wkl,g_wkl);
    cudaGetSymbolAddress((void**)&wvh,g_wvh); cudaGetSymbolAddress((void**)&wvl,g_wvl);
    cudaGetSymbolAddress((void**)&woh,g_woh); cudaGetSymbolAddress((void**)&wol,g_wol);
    cudaGetSymbolAddress((void**)&qh,g_qh);   cudaGetSymbolAddress((void**)&ql,g_ql);
    cudaGetSymbolAddress((void**)&kh,g_kh);   cudaGetSymbolAddress((void**)&kl,g_kl);
    cudaGetSymbolAddress((void**)&vh,g_vh);   cudaGetSymbolAddress((void**)&vl,g_vl);
    cudaGetSymbolAddress((void**)&ch,g_ch);   cudaGetSymbolAddress((void**)&cl,g_cl);

    cudaFuncSetAttribute(gemm_bf,    cudaFuncAttributeMaxDynamicSharedMemorySize, 221184);
    cudaFuncSetAttribute(attn_kernel,cudaFuncAttributeMaxDynamicSharedMemorySize, 184320);

    // splits: 3 inputs batched, 4 weights batched
    {
        SplitArgs si; si.x[0]=query; si.x[1]=key; si.x[2]=value; si.x[3]=query;
        si.h[0]=iqh; si.h[1]=ikh; si.h[2]=ivh; si.h[3]=iqh;
        si.l[0]=iql; si.l[1]=ikl; si.l[2]=ivl; si.l[3]=iql;
        int n4=(NB*NL*ND)/4;
        splitN<<<dim3((n4+255)/256,3),256>>>(si,n4);
        SplitArgs sw; sw.x[0]=wq; sw.x[1]=wk; sw.x[2]=wv; sw.x[3]=wo;
        sw.h[0]=wqh; sw.h[1]=wkh; sw.h[2]=wvh; sw.h[3]=woh;
        sw.l[0]=wql; sw.l[1]=wkl; sw.l[2]=wvl; sw.l[3]=wol;
        int m4=(ND*ND)/4;
        splitN<<<dim3((m4+255)/256,4),256>>>(sw,m4);
    }

    // QKV projections batched (grid.z = 3)
    {
        GArgs ga;
        ga.xh[0]=iqh; ga.xl[0]=iql; ga.wh[0]=wqh; ga.wl[0]=wql; ga.oh[0]=qh; ga.ol[0]=ql; ga.of[0]=nullptr;
        ga.xh[1]=ikh; ga.xl[1]=ikl; ga.wh[1]=wkh; ga.wl[1]=wkl; ga.oh[1]=kh; ga.ol[1]=kl; ga.of[1]=nullptr;
        ga.xh[2]=ivh; ga.xl[2]=ivl; ga.wh[2]=wvh; ga.wl[2]=wvl; ga.oh[2]=vh; ga.ol[2]=vl; ga.of[2]=nullptr;
        gemm_bf<<<dim3(8,32,3),256,221184>>>(ga);
    }

    attn_kernel<<<dim3(16,32),256,184320>>>(qh,ql,kh,kl,vh,vl,attn,ch,cl);

    // out projection
    {
        GArgs ga;
        ga.xh[0]=ch; ga.xl[0]=cl; ga.wh[0]=woh; ga.wl[0]=wol; ga.oh[0]=nullptr; ga.ol[0]=nullptr; ga.of[0]=out;
        ga.xh[1]=ch; ga.xl[1]=cl; ga.wh[1]=woh; ga.wl[1]=wol; ga.oh[1]=nullptr; ga.ol[1]=nullptr; ga.of[1]=out;
        ga.xh[2]=ch; ga.xl[2]=cl; ga.wh[2]=woh; ga.wl[2]=wol; ga.oh[2]=nullptr; ga.ol[2]=nullptr; ga.of[2]=out;
        gemm_bf<<<dim3(8,32,1),256,221184>>>(ga);
    }
}